// round 8
// baseline (speedup 1.0000x reference)
#include <cuda_runtime.h>

#define N_NODES 100000
#define N_EDGES 1600000
#define NFEAT   48
#define HIDDEN  256
#define TILE    128              // nodes per dot tile
#define TPB     256
#define NB      296              // 2 blocks/SM on 148 SMs (152 on GB300: still fine)
#define GSZ     (NB * TPB)

// Scratch (no device allocation allowed -> __device__ globals)
__device__ float g_c;            // fused bias term
__device__ float g_deg[N_NODES]; // degree (incl. self loop)
__device__ float g_dinv[N_NODES];
__device__ float g_z[N_NODES];   // y = x.w, then z = y*dinv (in place)
__device__ unsigned int g_bar_arrive  = 0;
__device__ unsigned int g_bar_release = 0;

// Grid-wide barrier: single arrive counter (auto-wrap via atomicInc) + monotone
// release generation. gen MUST be read (and fenced) before arriving, else a
// late-completing gen read can observe the release of this very barrier and
// spin on the next generation -> deadlock.
__device__ __forceinline__ void grid_bar() {
    __syncthreads();
    if (threadIdx.x == 0) {
        __threadfence();                                  // publish phase writes
        unsigned int gen = atomicAdd(&g_bar_release, 0u); // ordered read
        __threadfence();
        if (atomicInc(&g_bar_arrive, NB - 1) == NB - 1) {
            atomicAdd(&g_bar_release, 1u);                // last arriver releases
        } else {
            volatile unsigned int* rel = &g_bar_release;
            while (*rel == gen) { __nanosleep(32); }
        }
        __threadfence();                                  // acquire
    }
    __syncthreads();
}

__global__ void __launch_bounds__(TPB, 2)
k_fused(const float* __restrict__ x, const int* __restrict__ ei,
        const float* __restrict__ W1, const float* __restrict__ bias,
        const float* __restrict__ W2, const float* __restrict__ b2,
        float* __restrict__ out) {
    __shared__ float sbuf[TILE * 49];   // dot tile (stride-49: conflict-free) / P0 reduce
    __shared__ float s_w2[HIDDEN];
    __shared__ float sw[NFEAT];

    const int t   = threadIdx.x;
    const int bid = blockIdx.x;
    const int gid = bid * TPB + t;

    // ================= P0: deg = 1 (self loop); block 0: g_c =================
    {
        float4 one = make_float4(1.f, 1.f, 1.f, 1.f);
        for (int i = gid; i < N_NODES / 4; i += GSZ)
            __stcg(&reinterpret_cast<float4*>(g_deg)[i], one);   // L1-bypass: P1 atomics hit L2
    }
    if (bid == 0) {
        sbuf[t] = __ldg(&W2[t]);        // TPB == HIDDEN
        __syncthreads();
        for (int s = HIDDEN / 2; s > 0; s >>= 1) {
            if (t < s) sbuf[t] += sbuf[t + s];
            __syncthreads();
        }
        if (t == 0) g_c = bias[0] * sbuf[0] + b2[0];
    }
    grid_bar();

    // ================= P1: split blocks: 1/4 dot (DRAM), 3/4 count (atomics) =
    if ((bid & 3) == 0) {
        // ---- dot worker: y[i] = x[i] . (W1@W2) ----
        // Each dot block computes its own fused weight vector (W1/W2 are tiny,
        // L2-resident; avoids serializing on a producer block).
        s_w2[t] = __ldg(&W2[t]);
        __syncthreads();
        if (t < NFEAT) {
            const float* r = W1 + t * HIDDEN;
            float acc = 0.f;
#pragma unroll 8
            for (int h = 0; h < HIDDEN; ++h) acc = fmaf(__ldg(&r[h]), s_w2[h], acc);
            sw[t] = acc;
        }

        const int ND = NB / 4;                       // 74 dot blocks
        const int nTiles = (N_NODES + TILE - 1) / TILE;
        for (int tile = (bid >> 2); tile < nTiles; tile += ND) {
            int base = tile * TILE;
            int nn   = min(TILE, N_NODES - base);
            const float4* src = reinterpret_cast<const float4*>(x + (size_t)base * NFEAT);
            int nf4 = nn * (NFEAT / 4);
            __syncthreads();                         // sbuf reuse fence
            for (int idx = t; idx < nf4; idx += TPB) {
                float4 v = __ldg(&src[idx]);
                int node = idx / 12;
                int f4   = idx - node * 12;
                float* d = &sbuf[node * 49 + f4 * 4];
                d[0] = v.x; d[1] = v.y; d[2] = v.z; d[3] = v.w;
            }
            __syncthreads();
            if (t < nn) {
                const float* r = &sbuf[t * 49];
                float a0 = 0.f, a1 = 0.f, a2 = 0.f, a3 = 0.f;
#pragma unroll
                for (int k = 0; k < NFEAT; k += 4) {
                    a0 = fmaf(r[k + 0], sw[k + 0], a0);
                    a1 = fmaf(r[k + 1], sw[k + 1], a1);
                    a2 = fmaf(r[k + 2], sw[k + 2], a2);
                    a3 = fmaf(r[k + 3], sw[k + 3], a3);
                }
                __stcg(&g_z[base + t], (a0 + a1) + (a2 + a3));  // no L1 copy -> P3 safe
            }
        }
    } else {
        // ---- count worker: deg[col] += 1 over edges ----
        const int w  = bid - (bid >> 2) - 1;         // 0..221
        const int NW = NB - NB / 4;                  // 222 count blocks
        const int4* cols = reinterpret_cast<const int4*>(ei + N_EDGES);
        for (int i = w * TPB + t; i < N_EDGES / 4; i += NW * TPB) {
            int4 c = __ldg(&cols[i]);
            atomicAdd(&g_deg[c.x], 1.0f);
            atomicAdd(&g_deg[c.y], 1.0f);
            atomicAdd(&g_deg[c.z], 1.0f);
            atomicAdd(&g_deg[c.w], 1.0f);
        }
    }
    grid_bar();

    // ================= P2: z = y*rsqrt(deg); out = z; store dinv ==============
    for (int i = gid; i < N_NODES / 4; i += GSZ) {
        float4 y = __ldcg(&reinterpret_cast<const float4*>(g_z)[i]);
        float4 d = __ldcg(&reinterpret_cast<const float4*>(g_deg)[i]);
        float4 di = make_float4(rsqrtf(d.x), rsqrtf(d.y), rsqrtf(d.z), rsqrtf(d.w));
        float4 z  = make_float4(y.x * di.x, y.y * di.y, y.z * di.z, y.w * di.w);
        __stcg(&reinterpret_cast<float4*>(g_dinv)[i], di);
        __stcg(&reinterpret_cast<float4*>(g_z)[i],    z);   // no stale L1 anywhere
        __stcg(&reinterpret_cast<float4*>(out)[i],    z);   // self-loop term
    }
    grid_bar();

    // ================= P3: scatter out[col] += z[row] ========================
    {
        const int4* rows = reinterpret_cast<const int4*>(ei);
        const int4* cols = reinterpret_cast<const int4*>(ei + N_EDGES);
        for (int i = gid; i < N_EDGES / 4; i += GSZ) {
            int4 r = __ldg(&rows[i]);
            int4 c = __ldg(&cols[i]);
            float z0 = __ldg(&g_z[r.x]);             // L1-cacheable: only fresh copies exist
            float z1 = __ldg(&g_z[r.y]);
            float z2 = __ldg(&g_z[r.z]);
            float z3 = __ldg(&g_z[r.w]);
            atomicAdd(&out[c.x], z0);
            atomicAdd(&out[c.y], z1);
            atomicAdd(&out[c.z], z2);
            atomicAdd(&out[c.w], z3);
        }
    }
    grid_bar();

    // ================= P4: out = out*dinv + c ================================
    {
        float c = g_c;
        for (int i = gid; i < N_NODES / 4; i += GSZ) {
            float4 o = __ldcg(&reinterpret_cast<const float4*>(out)[i]);  // values live in L2
            float4 d = __ldcg(&reinterpret_cast<const float4*>(g_dinv)[i]);
            o.x = fmaf(o.x, d.x, c);
            o.y = fmaf(o.y, d.y, c);
            o.z = fmaf(o.z, d.z, c);
            o.w = fmaf(o.w, d.w, c);
            reinterpret_cast<float4*>(out)[i] = o;
        }
    }
}

extern "C" void kernel_launch(void* const* d_in, const int* in_sizes, int n_in,
                              void* d_out, int out_size) {
    const float* x    = (const float*)d_in[0];
    const int*   ei   = (const int*)  d_in[1];
    const float* W1   = (const float*)d_in[2];
    const float* bias = (const float*)d_in[3];
    const float* W2   = (const float*)d_in[4];
    const float* b2   = (const float*)d_in[5];
    float* out = (float*)d_out;

    k_fused<<<NB, TPB>>>(x, ei, W1, bias, W2, b2, out);
}

// round 10
// speedup vs baseline: 1.1566x; 1.1566x over previous
#include <cuda_runtime.h>

#define N_NODES 100000
#define N_EDGES 1600000
#define NFEAT   48
#define HIDDEN  256
#define TILE    128   // nodes per block in k_dot

// Scratch (no device allocation allowed -> __device__ globals)
__device__ float        g_w[NFEAT];     // fused W1@W2
__device__ float        g_c;            // fused bias term
__device__ unsigned int g_deg[N_NODES]; // edge-in count (self loop added in k_z)
__device__ float        g_dinv[N_NODES];
__device__ float        g_z[N_NODES];   // y = x.w, then z = y*dinv (in place)

// ---- side stream A1: w = W1@W2, c = bias*sum(W2)+b2 ----
__global__ void k_fuse_w(const float* __restrict__ W1,
                         const float* __restrict__ bias,
                         const float* __restrict__ W2,
                         const float* __restrict__ b2) {
    __shared__ float s_w2[HIDDEN];
    int t = threadIdx.x;              // blockDim == HIDDEN == 256
    s_w2[t] = W2[t];
    __syncthreads();
    if (t < NFEAT) {
        const float* r = W1 + t * HIDDEN;
        float acc = 0.f;
#pragma unroll 8
        for (int h = 0; h < HIDDEN; ++h) acc = fmaf(r[h], s_w2[h], acc);
        g_w[t] = acc;
    }
    if (t == 0) {
        float s = 0.f;
        for (int h = 0; h < HIDDEN; ++h) s += s_w2[h];
        g_c = bias[0] * s + b2[0];
    }
}

// ---- side stream A2: y[i] = x[i].w  (coalesced via padded smem tile) ----
__global__ void __launch_bounds__(TILE) k_dot(const float* __restrict__ x) {
    __shared__ float sx[TILE * 49];   // stride-49 padding: conflict-free reads
    __shared__ float sw[NFEAT];

    int t    = threadIdx.x;
    int tile = blockIdx.x * TILE;
    int nn   = min(TILE, N_NODES - tile);

    if (t < NFEAT) sw[t] = g_w[t];

    const float4* src = reinterpret_cast<const float4*>(x + (size_t)tile * NFEAT);
    int nf4 = nn * (NFEAT / 4);
    for (int idx = t; idx < nf4; idx += TILE) {
        float4 v = __ldg(&src[idx]);
        int node = idx / 12;
        int f4   = idx - node * 12;
        float* d = &sx[node * 49 + f4 * 4];
        d[0] = v.x; d[1] = v.y; d[2] = v.z; d[3] = v.w;
    }
    __syncthreads();

    if (t < nn) {
        const float* r = &sx[t * 49];
        float a0 = 0.f, a1 = 0.f, a2 = 0.f, a3 = 0.f;
#pragma unroll
        for (int k = 0; k < NFEAT; k += 4) {
            a0 = fmaf(r[k + 0], sw[k + 0], a0);
            a1 = fmaf(r[k + 1], sw[k + 1], a1);
            a2 = fmaf(r[k + 2], sw[k + 2], a2);
            a3 = fmaf(r[k + 3], sw[k + 3], a3);
        }
        g_z[tile + t] = (a0 + a1) + (a2 + a3);   // y (dinv applied in k_z)
    }
}

// ---- main stream: degree count (u32), 4 edges per thread ----
__global__ void k_count(const int* __restrict__ ei) {
    int t = blockIdx.x * blockDim.x + threadIdx.x;
    if (t < N_EDGES / 4) {
        const int4* cols = reinterpret_cast<const int4*>(ei + N_EDGES);
        int4 c = __ldg(&cols[t]);
        atomicAdd(&g_deg[c.x], 1u);
        atomicAdd(&g_deg[c.y], 1u);
        atomicAdd(&g_deg[c.z], 1u);
        atomicAdd(&g_deg[c.w], 1u);
    }
}

// ---- join: dinv = rsqrt(deg+1); z = y*dinv; out = z*dinv + c ----
__global__ void k_z(float* __restrict__ out) {
    int t = blockIdx.x * blockDim.x + threadIdx.x;
    if (t < N_NODES / 4) {   // 100000 % 4 == 0
        uint4  dg = reinterpret_cast<const uint4*>(g_deg)[t];
        float4 y  = reinterpret_cast<const float4*>(g_z)[t];
        float4 di = make_float4(rsqrtf((float)(dg.x + 1u)),
                                rsqrtf((float)(dg.y + 1u)),
                                rsqrtf((float)(dg.z + 1u)),
                                rsqrtf((float)(dg.w + 1u)));
        float4 z  = make_float4(y.x * di.x, y.y * di.y, y.z * di.z, y.w * di.w);
        float  c  = g_c;
        reinterpret_cast<float4*>(g_dinv)[t] = di;
        reinterpret_cast<float4*>(g_z)[t]    = z;
        // self-loop term with final normalization + bias folded in
        reinterpret_cast<float4*>(out)[t] =
            make_float4(fmaf(z.x, di.x, c), fmaf(z.y, di.y, c),
                        fmaf(z.z, di.z, c), fmaf(z.w, di.w, c));
    }
}

// ---- scatter + final fused: out[col] += z[row] * dinv[col] ----
__global__ void k_scatter(const int* __restrict__ ei, float* __restrict__ out) {
    int t = blockIdx.x * blockDim.x + threadIdx.x;
    if (t < N_EDGES / 4) {
        const int4* rows = reinterpret_cast<const int4*>(ei);
        const int4* cols = reinterpret_cast<const int4*>(ei + N_EDGES);
        int4 r = __ldg(&rows[t]);
        int4 c = __ldg(&cols[t]);
        float z0 = __ldg(&g_z[r.x]);
        float z1 = __ldg(&g_z[r.y]);
        float z2 = __ldg(&g_z[r.z]);
        float z3 = __ldg(&g_z[r.w]);
        float d0 = __ldg(&g_dinv[c.x]);
        float d1 = __ldg(&g_dinv[c.y]);
        float d2 = __ldg(&g_dinv[c.z]);
        float d3 = __ldg(&g_dinv[c.w]);
        atomicAdd(&out[c.x], z0 * d0);
        atomicAdd(&out[c.y], z1 * d1);
        atomicAdd(&out[c.z], z2 * d2);
        atomicAdd(&out[c.w], z3 * d3);
    }
}

extern "C" void kernel_launch(void* const* d_in, const int* in_sizes, int n_in,
                              void* d_out, int out_size) {
    const float* x    = (const float*)d_in[0];
    const int*   ei   = (const int*)  d_in[1];
    const float* W1   = (const float*)d_in[2];
    const float* bias = (const float*)d_in[3];
    const float* W2   = (const float*)d_in[4];
    const float* b2   = (const float*)d_in[5];
    float* out = (float*)d_out;

    const int TB = 256;
    const int nb_n4   = (N_NODES / 4 + TB - 1) / TB;   // 98
    const int nb_e4   = (N_EDGES / 4 + TB - 1) / TB;   // 1563
    const int nb_node = (N_NODES + TILE - 1) / TILE;   // 782

    // Degree init: memset node (free) instead of a kernel.
    void* deg_ptr = nullptr;
    cudaGetSymbolAddress(&deg_ptr, g_deg);
    cudaMemsetAsync(deg_ptr, 0, N_NODES * sizeof(unsigned int), 0);

    // Fork: (fuse_w -> dot) DRAM-bound chain overlaps (memset -> count)
    // atomic-bound chain. Host-side stream/event creation only (no device
    // memory); leaked intentionally - kernel_launch is called a bounded
    // number of times (correctness + capture).
    cudaStream_t s1;
    cudaEvent_t  eFork, eJoin;
    cudaStreamCreateWithFlags(&s1, cudaStreamNonBlocking);
    cudaEventCreateWithFlags(&eFork, cudaEventDisableTiming);
    cudaEventCreateWithFlags(&eJoin, cudaEventDisableTiming);

    cudaEventRecord(eFork, 0);
    cudaStreamWaitEvent(s1, eFork, 0);

    k_fuse_w<<<1, HIDDEN, 0, s1>>>(W1, bias, W2, b2);
    k_dot   <<<nb_node, TILE, 0, s1>>>(x);
    cudaEventRecord(eJoin, s1);

    k_count <<<nb_e4, TB>>>(ei);

    cudaStreamWaitEvent(0, eJoin, 0);

    k_z      <<<nb_n4, TB>>>(out);
    k_scatter<<<nb_e4, TB>>>(ei, out);
}